// round 1
// baseline (speedup 1.0000x reference)
#include <cuda_runtime.h>
#include <math.h>

#define TT 196          // tokens = 14*14
#define CC 640          // channels
#define TPB 1024        // threads per block
#define NW (TPB/32)     // 32 warps
#define CSPLIT 4
#define CCHUNK (CC/CSPLIT)  // 160

__device__ __forceinline__ float warp_sum(float v) {
#pragma unroll
    for (int o = 16; o; o >>= 1) v += __shfl_xor_sync(0xffffffffu, v, o);
    return v;
}
__device__ __forceinline__ float warp_max(float v) {
#pragma unroll
    for (int o = 16; o; o >>= 1) v = fmaxf(v, __shfl_xor_sync(0xffffffffu, v, o));
    return v;
}

struct Smem {
    float invnc[TT], invnq[TT];   // 1/||token|| for class / query
    float cbar[CC], qbar[CC];     // mean normalized token
    float mc[TT], mq[TT];         // corr means
    float kc[TT], kq[TT];         // MLP outputs
    float vc[CC], vq[CC];         // k-weighted token sums
    float ac[TT], aq[TT];         // logits -> attention
    float part[CSPLIT][TT];       // column-pass partials
    float w[TT];                  // scratch weight vector for row passes
    float h[64];                  // MLP hidden (class 0..31, query 32..63)
    float red[2];                 // softmax reduction scratch
};

// out[t] = sum_c X[c][t]^2   (column-wise squared sums)
__device__ __forceinline__ void col_sq(const float* __restrict__ X, Smem& s,
                                       int grp, int j, int tid, float* out) {
    if (j < TT) {
        const float* p = X + (size_t)(grp * CCHUNK) * TT + j;
        float acc = 0.f;
#pragma unroll 8
        for (int c = 0; c < CCHUNK; ++c) {
            float v = p[(size_t)c * TT];
            acc = fmaf(v, v, acc);
        }
        s.part[grp][j] = acc;
    }
    __syncthreads();
    if (tid < TT)
        out[tid] = s.part[0][tid] + s.part[1][tid] + s.part[2][tid] + s.part[3][tid];
    __syncthreads();
}

// out[t] = sum_c wv[c] * X[c][t]   (weighted column sums)
__device__ __forceinline__ void col_w(const float* __restrict__ X,
                                      const float* __restrict__ wv, Smem& s,
                                      int grp, int j, int tid, float* out) {
    if (j < TT) {
        const float* p = X + (size_t)(grp * CCHUNK) * TT + j;
        const float* wp = wv + grp * CCHUNK;
        float acc = 0.f;
#pragma unroll 8
        for (int c = 0; c < CCHUNK; ++c)
            acc = fmaf(wp[c], p[(size_t)c * TT], acc);
        s.part[grp][j] = acc;
    }
    __syncthreads();
    if (tid < TT)
        out[tid] = s.part[0][tid] + s.part[1][tid] + s.part[2][tid] + s.part[3][tid];
    __syncthreads();
}

// out[c] = scale * sum_t wv[t] * X[c][t]   (weighted row sums)
__device__ __forceinline__ void row_w(const float* __restrict__ X,
                                      const float* __restrict__ wv,
                                      float* __restrict__ out, float scale,
                                      int wid, int lane) {
    for (int c = wid; c < CC; c += NW) {
        const float* p = X + (size_t)c * TT;
        float acc = 0.f;
        for (int t = lane; t < TT; t += 32)
            acc = fmaf(wv[t], p[t], acc);
        acc = warp_sum(acc);
        if (lane == 0) out[c] = acc * scale;
    }
    __syncthreads();
}

__device__ __forceinline__ void softmax_inplace(float* buf, Smem& s,
                                                int tid, int wid, int lane) {
    if (wid == 0) {
        float v = -3.4e38f;
        for (int t = lane; t < TT; t += 32) v = fmaxf(v, buf[t]);
        v = warp_max(v);
        if (lane == 0) s.red[0] = v;
    }
    __syncthreads();
    float mx = s.red[0];
    if (tid < TT) buf[tid] = expf(buf[tid] - mx);
    __syncthreads();
    if (wid == 0) {
        float v = 0.f;
        for (int t = lane; t < TT; t += 32) v += buf[t];
        v = warp_sum(v);
        if (lane == 0) s.red[1] = v;
    }
    __syncthreads();
    float inv = 1.f / s.red[1];
    if (tid < TT) buf[tid] *= inv;
    __syncthreads();
}

__global__ void __launch_bounds__(TPB, 1)
cross_attn_kernel(const float* __restrict__ cls_all, const float* __restrict__ qry_all,
                  const float* __restrict__ cw1, const float* __restrict__ cb1,
                  const float* __restrict__ cw2, const float* __restrict__ cb2,
                  const float* __restrict__ qw1, const float* __restrict__ qb1,
                  const float* __restrict__ qw2, const float* __restrict__ qb2,
                  float* __restrict__ oc_all, float* __restrict__ oq_all) {
    extern __shared__ float occupancy_blocker[];  // only to cap 1 CTA/SM (L2 residency)
    (void)occupancy_blocker;
    __shared__ Smem s;

    const int tid  = threadIdx.x;
    const int grp  = tid >> 8;    // 0..3 (channel split for column passes)
    const int j    = tid & 255;   // lane within split, active if < TT
    const int wid  = tid >> 5;
    const int lane = tid & 31;

    const size_t off = (size_t)blockIdx.x * (CC * TT);
    const float* Xc = cls_all + off;
    const float* Xq = qry_all + off;

    // ---- Phase 1: per-token inverse L2 norms --------------------------------
    col_sq(Xc, s, grp, j, tid, s.invnc);
    if (tid < TT) s.invnc[tid] = 1.f / fmaxf(sqrtf(s.invnc[tid]), 1e-12f);
    col_sq(Xq, s, grp, j, tid, s.invnq);
    if (tid < TT) s.invnq[tid] = 1.f / fmaxf(sqrtf(s.invnq[tid]), 1e-12f);
    __syncthreads();

    // ---- Phase 2: cbar = mean_t ct[t], qbar = mean_t qt[t] ------------------
    row_w(Xc, s.invnc, s.cbar, 1.f / (float)TT, wid, lane);
    row_w(Xq, s.invnq, s.qbar, 1.f / (float)TT, wid, lane);

    // ---- Phase 3: m_c[u] = cbar . qt[u],  m_q[u] = qbar . ct[u] -------------
    col_w(Xq, s.cbar, s, grp, j, tid, s.mc);
    if (tid < TT) s.mc[tid] *= s.invnq[tid];
    col_w(Xc, s.qbar, s, grp, j, tid, s.mq);
    if (tid < TT) s.mq[tid] *= s.invnc[tid];
    __syncthreads();

    // ---- Phase 4: tiny MLPs  k = relu(m@w1+b1)@w2+b2 ------------------------
    if (tid < 64) {
        const bool isC = tid < 32;
        const float* w1 = isC ? cw1 : qw1;
        const float* b1 = isC ? cb1 : qb1;
        const float* m  = isC ? s.mc : s.mq;
        const int hh = tid & 31;
        float acc = b1[hh];
        for (int t = 0; t < TT; ++t)
            acc = fmaf(m[t], w1[t * 32 + hh], acc);
        s.h[tid] = fmaxf(acc, 0.f);
    }
    __syncthreads();
    if (grp < 2 && j < TT) {
        const bool isC = (grp == 0);
        const float* w2 = isC ? cw2 : qw2;
        const float* b2 = isC ? cb2 : qb2;
        const float* hp = s.h + (isC ? 0 : 32);
        float acc = b2[j];
#pragma unroll
        for (int hh = 0; hh < 32; ++hh)
            acc = fmaf(hp[hh], w2[hh * TT + j], acc);
        (isC ? s.kc : s.kq)[j] = acc;
    }
    __syncthreads();

    // ---- Phase 5: v_c = sum_u kc[u]*qt[u],  v_q = sum_t kq[t]*ct[t] ---------
    if (tid < TT) s.w[tid] = s.kc[tid] * s.invnq[tid];
    __syncthreads();
    row_w(Xq, s.w, s.vc, 1.f, wid, lane);
    if (tid < TT) s.w[tid] = s.kq[tid] * s.invnc[tid];
    __syncthreads();
    row_w(Xc, s.w, s.vq, 1.f, wid, lane);

    // ---- Phase 6: logits + softmax ------------------------------------------
    col_w(Xc, s.vc, s, grp, j, tid, s.ac);
    if (tid < TT) s.ac[tid] = s.ac[tid] * s.invnc[tid] / 0.025f;
    __syncthreads();
    softmax_inplace(s.ac, s, tid, wid, lane);

    col_w(Xq, s.vq, s, grp, j, tid, s.aq);
    if (tid < TT) s.aq[tid] = s.aq[tid] * s.invnq[tid] / 0.025f;
    __syncthreads();
    softmax_inplace(s.aq, s, tid, wid, lane);

    // ---- Phase 7: out = feat * (1 + attn[token]) ----------------------------
    const float4* xc4 = reinterpret_cast<const float4*>(Xc);
    const float4* xq4 = reinterpret_cast<const float4*>(Xq);
    float4* oc4 = reinterpret_cast<float4*>(oc_all + off);
    float4* oq4 = reinterpret_cast<float4*>(oq_all + off);
    const int N4 = CC * TT / 4;  // 31360, token stride 196 is divisible by 4
    for (int i = tid; i < N4; i += TPB) {
        int t0 = (i % 49) * 4;   // token index of first element in this float4
        float a0 = 1.f + s.ac[t0], a1 = 1.f + s.ac[t0 + 1];
        float a2 = 1.f + s.ac[t0 + 2], a3 = 1.f + s.ac[t0 + 3];
        float4 v = xc4[i];
        v.x *= a0; v.y *= a1; v.z *= a2; v.w *= a3;
        oc4[i] = v;
        float b0 = 1.f + s.aq[t0], b1 = 1.f + s.aq[t0 + 1];
        float b2 = 1.f + s.aq[t0 + 2], b3 = 1.f + s.aq[t0 + 3];
        float4 u = xq4[i];
        u.x *= b0; u.y *= b1; u.z *= b2; u.w *= b3;
        oq4[i] = u;
    }
}

extern "C" void kernel_launch(void* const* d_in, const int* in_sizes, int n_in,
                              void* d_out, int out_size) {
    const float* cls = (const float*)d_in[0];
    const float* qry = (const float*)d_in[1];
    const float* cw1 = (const float*)d_in[2];
    const float* cb1 = (const float*)d_in[3];
    const float* cw2 = (const float*)d_in[4];
    const float* cb2 = (const float*)d_in[5];
    const float* qw1 = (const float*)d_in[6];
    const float* qb1 = (const float*)d_in[7];
    const float* qw2 = (const float*)d_in[8];
    const float* qb2 = (const float*)d_in[9];

    const int B = in_sizes[0] / (CC * TT);  // 512
    float* oc = (float*)d_out;
    float* oq = oc + (size_t)B * CC * TT;

    // Dynamic smem used only to force 1 CTA/SM so each resident batch's ~1MB
    // working set stays L2-hot across the kernel's 12 data sweeps.
    const int DYN_SMEM = 96 * 1024;
    cudaFuncSetAttribute(cross_attn_kernel,
                         cudaFuncAttributeMaxDynamicSharedMemorySize, DYN_SMEM);

    cross_attn_kernel<<<B, TPB, DYN_SMEM>>>(cls, qry,
                                            cw1, cb1, cw2, cb2,
                                            qw1, qb1, qw2, qb2,
                                            oc, oq);
}

// round 2
// speedup vs baseline: 1.5766x; 1.5766x over previous
#include <cuda_runtime.h>
#include <cooperative_groups.h>
#include <math.h>

namespace cg = cooperative_groups;

#define TT 196            // tokens
#define CC 640            // channels
#define CLN 8             // cluster size: 4 chunks x 2 tensors
#define CHUNK 160         // channels per CTA
#define TPB 256
#define NW 8
#define TILE_ELEMS (CHUNK * TT)        // 31360
#define TILE_BYTES (TILE_ELEMS * 4)    // 125440 (multiple of 16)

__device__ __forceinline__ float warp_sum(float v) {
#pragma unroll
    for (int o = 16; o; o >>= 1) v += __shfl_xor_sync(0xffffffffu, v, o);
    return v;
}
__device__ __forceinline__ float warp_max(float v) {
#pragma unroll
    for (int o = 16; o; o >>= 1) v = fmaxf(v, __shfl_xor_sync(0xffffffffu, v, o));
    return v;
}

__device__ __forceinline__ unsigned su32(const void* p) {
    unsigned a;
    asm("{ .reg .u64 t; cvta.to.shared.u64 t, %1; cvt.u32.u64 %0, t; }"
        : "=r"(a) : "l"(p));
    return a;
}

__device__ __forceinline__ void mbar_init(unsigned mb, unsigned cnt) {
    asm volatile("mbarrier.init.shared.b64 [%0], %1;" :: "r"(mb), "r"(cnt) : "memory");
}
__device__ __forceinline__ void mbar_expect_tx(unsigned mb, unsigned bytes) {
    asm volatile("mbarrier.arrive.expect_tx.shared.b64 _, [%0], %1;"
                 :: "r"(mb), "r"(bytes) : "memory");
}
__device__ __forceinline__ void mbar_wait(unsigned mb, unsigned parity) {
    asm volatile(
        "{\n\t.reg .pred p;\n\t"
        "WL_%=:\n\t"
        "mbarrier.try_wait.parity.shared.b64 p, [%0], %1;\n\t"
        "@!p bra WL_%=;\n\t}"
        :: "r"(mb), "r"(parity) : "memory");
}
__device__ __forceinline__ void bulk_g2s(unsigned dst, const void* src,
                                         unsigned bytes, unsigned mb) {
    asm volatile(
        "cp.async.bulk.shared::cta.global.mbarrier::complete_tx::bytes "
        "[%0], [%1], %2, [%3];"
        :: "r"(dst), "l"(src), "r"(bytes), "r"(mb) : "memory");
}

struct State {
    alignas(16) float a4[TT];   // 1 + attn (float4-readable)
    float p0[TT];               // sumsq partials (remote-read by group)
    float bar[CHUNK];           // my bar chunk  (remote-read by peer)
    float mpart[TT];            // m partials    (remote-read by group)
    float v[CHUNK];             // my v chunk    (remote-read by peer)
    float lp[TT];               // logit partials(remote-read by group)
    float obar[CHUNK];          // local scratch: peer bar / peer v copy
    float invn[TT];             // local
    float m[TT];                // local: m, then logits
    float kw[TT];               // local: k * invn
    float h[32];                // MLP hidden
    float red[2];               // softmax reduce
    alignas(8) unsigned long long mbar;
};

__global__ void __launch_bounds__(TPB, 1) __cluster_dims__(CLN, 1, 1)
cross_attn_cluster(const float* __restrict__ cls_all, const float* __restrict__ qry_all,
                   const float* __restrict__ cw1, const float* __restrict__ cb1,
                   const float* __restrict__ cw2, const float* __restrict__ cb2,
                   const float* __restrict__ qw1, const float* __restrict__ qb1,
                   const float* __restrict__ qw2, const float* __restrict__ qb2,
                   float* __restrict__ oc_all, float* __restrict__ oq_all) {
    extern __shared__ float tile[];   // [CHUNK][TT]
    __shared__ State s;

    cg::cluster_group cl = cg::this_cluster();
    const int tid  = threadIdx.x;
    const int lane = tid & 31;
    const int wid  = tid >> 5;
    const unsigned rank  = cl.block_rank();           // 0..7
    const bool isClass   = rank < 4;
    const unsigned chunk = rank & 3;
    const unsigned gbase = isClass ? 0u : 4u;
    const unsigned peer  = isClass ? rank + 4 : rank - 4;
    const int batch = blockIdx.x / CLN;

    const size_t off = (size_t)batch * CC * TT + (size_t)chunk * CHUNK * TT;
    const float* X = (isClass ? cls_all : qry_all) + off;
    float*       O = (isClass ? oc_all  : oq_all ) + off;

    // Class CTAs evaluate the QUERY-side MLP (mq->kq) and vice versa.
    const float* w1 = isClass ? qw1 : cw1;
    const float* b1 = isClass ? qb1 : cb1;
    const float* w2 = isClass ? qw2 : cw2;
    const float* b2 = isClass ? qb2 : cb2;

    // ---- TMA bulk load of my tile ------------------------------------------
    const unsigned tileA = su32(tile);
    const unsigned mb    = su32(&s.mbar);
    if (tid == 0) mbar_init(mb, 1);
    __syncthreads();
    if (tid == 0) {
        mbar_expect_tx(mb, TILE_BYTES);
        bulk_g2s(tileA, X, TILE_BYTES, mb);
    }
    mbar_wait(mb, 0);

    // ---- Phase 1: sumsq partial over my channels ---------------------------
    if (tid < TT) {
        float acc = 0.f;
#pragma unroll 8
        for (int c = 0; c < CHUNK; ++c) {
            float v = tile[c * TT + tid];
            acc = fmaf(v, v, acc);
        }
        s.p0[tid] = acc;
    }
    cl.sync();  // S1

    // ---- invn (group reduce) + bar (local row reduce) ----------------------
    if (tid < TT) {
        float ss = 0.f;
#pragma unroll
        for (unsigned i = 0; i < 4; ++i)
            ss += cl.map_shared_rank(s.p0, gbase + i)[tid];
        s.invn[tid] = 1.f / fmaxf(sqrtf(ss), 1e-12f);
    }
    __syncthreads();
    for (int c = wid; c < CHUNK; c += NW) {
        float acc = 0.f;
        for (int t = lane; t < TT; t += 32)
            acc = fmaf(tile[c * TT + t], s.invn[t], acc);
        acc = warp_sum(acc);
        if (lane == 0) s.bar[c] = acc * (1.f / (float)TT);
    }
    cl.sync();  // S2

    // ---- m partial: sum_c peer_bar[c] * tile[c][t] -------------------------
    {
        const float* pbar = cl.map_shared_rank(s.bar, peer);
        if (tid < CHUNK) s.obar[tid] = pbar[tid];
    }
    __syncthreads();
    if (tid < TT) {
        float acc = 0.f;
#pragma unroll 8
        for (int c = 0; c < CHUNK; ++c)
            acc = fmaf(s.obar[c], tile[c * TT + tid], acc);
        s.mpart[tid] = acc;
    }
    cl.sync();  // S3

    // ---- m reduce, tiny MLP -> kw = k * invn, then v (local row reduce) ----
    if (tid < TT) {
        float mm = 0.f;
#pragma unroll
        for (unsigned i = 0; i < 4; ++i)
            mm += cl.map_shared_rank(s.mpart, gbase + i)[tid];
        s.m[tid] = mm * s.invn[tid];
    }
    __syncthreads();
    if (tid < 32) {
        float acc = b1[tid];
        for (int t = 0; t < TT; ++t)
            acc = fmaf(s.m[t], w1[t * 32 + tid], acc);
        s.h[tid] = fmaxf(acc, 0.f);
    }
    __syncthreads();
    if (tid < TT) {
        float acc = b2[tid];
#pragma unroll
        for (int hh = 0; hh < 32; ++hh)
            acc = fmaf(s.h[hh], w2[hh * TT + tid], acc);
        s.kw[tid] = acc * s.invn[tid];
    }
    __syncthreads();
    for (int c = wid; c < CHUNK; c += NW) {
        float acc = 0.f;
        for (int t = lane; t < TT; t += 32)
            acc = fmaf(tile[c * TT + t], s.kw[t], acc);
        acc = warp_sum(acc);
        if (lane == 0) s.v[c] = acc;
    }
    cl.sync();  // S4

    // ---- logit partial: sum_c peer_v[c] * tile[c][t] -----------------------
    {
        const float* pv = cl.map_shared_rank(s.v, peer);
        if (tid < CHUNK) s.obar[tid] = pv[tid];
    }
    __syncthreads();
    if (tid < TT) {
        float acc = 0.f;
#pragma unroll 8
        for (int c = 0; c < CHUNK; ++c)
            acc = fmaf(s.obar[c], tile[c * TT + tid], acc);
        s.lp[tid] = acc;
    }
    cl.sync();  // S5

    // ---- logits reduce, softmax (replicated within group) ------------------
    if (tid < TT) {
        float ll = 0.f;
#pragma unroll
        for (unsigned i = 0; i < 4; ++i)
            ll += cl.map_shared_rank(s.lp, gbase + i)[tid];
        s.m[tid] = ll * s.invn[tid] * 40.f;   // /0.025
    }
    __syncthreads();
    if (wid == 0) {
        float v = -3.4e38f;
        for (int t = lane; t < TT; t += 32) v = fmaxf(v, s.m[t]);
        v = warp_max(v);
        if (lane == 0) s.red[0] = v;
    }
    __syncthreads();
    if (tid < TT) s.m[tid] = expf(s.m[tid] - s.red[0]);
    __syncthreads();
    if (wid == 0) {
        float v = 0.f;
        for (int t = lane; t < TT; t += 32) v += s.m[t];
        v = warp_sum(v);
        if (lane == 0) s.red[1] = v;
    }
    __syncthreads();
    if (tid < TT) s.a4[tid] = 1.f + s.m[tid] / s.red[1];
    __syncthreads();

    // ---- output: out = tile * (1 + attn[token]) ----------------------------
    {
        const float4* t4 = reinterpret_cast<const float4*>(tile);
        const float4* a4 = reinterpret_cast<const float4*>(s.a4);
        float4* o4 = reinterpret_cast<float4*>(O);
        const int N4 = TILE_ELEMS / 4;   // 7840; row = 49 float4
        for (int i = tid; i < N4; i += TPB) {
            float4 v = t4[i];
            float4 a = a4[i % 49];
            v.x *= a.x; v.y *= a.y; v.z *= a.z; v.w *= a.w;
            o4[i] = v;
        }
    }

    cl.sync();  // keep SMEM alive until all cluster peers finished remote reads
}

extern "C" void kernel_launch(void* const* d_in, const int* in_sizes, int n_in,
                              void* d_out, int out_size) {
    const float* cls = (const float*)d_in[0];
    const float* qry = (const float*)d_in[1];
    const float* cw1 = (const float*)d_in[2];
    const float* cb1 = (const float*)d_in[3];
    const float* cw2 = (const float*)d_in[4];
    const float* cb2 = (const float*)d_in[5];
    const float* qw1 = (const float*)d_in[6];
    const float* qb1 = (const float*)d_in[7];
    const float* qw2 = (const float*)d_in[8];
    const float* qb2 = (const float*)d_in[9];

    const int B = in_sizes[0] / (CC * TT);  // 512
    float* oc = (float*)d_out;
    float* oq = oc + (size_t)B * CC * TT;

    cudaFuncSetAttribute(cross_attn_cluster,
                         cudaFuncAttributeMaxDynamicSharedMemorySize, TILE_BYTES);

    cross_attn_cluster<<<B * CLN, TPB, TILE_BYTES>>>(
        cls, qry, cw1, cb1, cw2, cb2, qw1, qb1, qw2, qb2, oc, oq);
}

// round 4
// speedup vs baseline: 2.3360x; 1.4817x over previous
#include <cuda_runtime.h>
#include <cooperative_groups.h>
#include <math.h>

namespace cg = cooperative_groups;

#define TT 196            // tokens
#define CC 640            // channels
#define CLN 16            // cluster: 8 channel-chunks x 2 tensors
#define CHUNK 80          // channels per CTA
#define TPB 256
#define NW 8
#define TILE_ELEMS (CHUNK * TT)        // 15680
#define TILE_BYTES (TILE_ELEMS * 4)    // 62720

__device__ __forceinline__ float warp_sum(float v) {
#pragma unroll
    for (int o = 16; o; o >>= 1) v += __shfl_xor_sync(0xffffffffu, v, o);
    return v;
}
__device__ __forceinline__ float warp_max(float v) {
#pragma unroll
    for (int o = 16; o; o >>= 1) v = fmaxf(v, __shfl_xor_sync(0xffffffffu, v, o));
    return v;
}

__device__ __forceinline__ unsigned su32(const void* p) {
    unsigned a;
    asm("{ .reg .u64 t; cvta.to.shared.u64 t, %1; cvt.u32.u64 %0, t; }"
        : "=r"(a) : "l"(p));
    return a;
}
__device__ __forceinline__ void mbar_init(unsigned mb, unsigned cnt) {
    asm volatile("mbarrier.init.shared.b64 [%0], %1;" :: "r"(mb), "r"(cnt) : "memory");
}
__device__ __forceinline__ void mbar_expect_tx(unsigned mb, unsigned bytes) {
    asm volatile("mbarrier.arrive.expect_tx.shared.b64 _, [%0], %1;"
                 :: "r"(mb), "r"(bytes) : "memory");
}
__device__ __forceinline__ void mbar_wait(unsigned mb, unsigned parity) {
    asm volatile(
        "{\n\t.reg .pred p;\n\t"
        "WL_%=:\n\t"
        "mbarrier.try_wait.parity.shared.b64 p, [%0], %1;\n\t"
        "@!p bra WL_%=;\n\t}"
        :: "r"(mb), "r"(parity) : "memory");
}
__device__ __forceinline__ void bulk_g2s(unsigned dst, const void* src,
                                         unsigned bytes, unsigned mb) {
    asm volatile(
        "cp.async.bulk.shared::cta.global.mbarrier::complete_tx::bytes "
        "[%0], [%1], %2, [%3];"
        :: "r"(dst), "l"(src), "r"(bytes), "r"(mb) : "memory");
}

struct State {
    alignas(16) float a4[TT];   // 1 + attn (float4-readable)
    float p0[TT];               // sumsq partials   (remote-read by group)
    float bar[CHUNK];           // my bar chunk     (remote-read by peer)
    float mpart[TT];            // m partials       (remote-read by group)
    float v[CHUNK];             // my v chunk       (remote-read by peer)
    float lp[TT];               // logit partials   (remote-read by group)
    float obar[CHUNK];          // local copy of peer bar / peer v
    float invn[TT];             // local
    float m[TT];                // local: m, then logits
    float kw[TT];               // local: k * invn
    float h[32];                // MLP hidden
    float red[2];               // softmax reduce
    alignas(8) unsigned long long mbar;
};

__global__ void __launch_bounds__(TPB, 2)
cross_attn_cluster16(const float* __restrict__ cls_all, const float* __restrict__ qry_all,
                     const float* __restrict__ cw1, const float* __restrict__ cb1,
                     const float* __restrict__ cw2, const float* __restrict__ cb2,
                     const float* __restrict__ qw1, const float* __restrict__ qb1,
                     const float* __restrict__ qw2, const float* __restrict__ qb2,
                     float* __restrict__ oc_all, float* __restrict__ oq_all) {
    extern __shared__ float tile[];   // [CHUNK][TT]
    __shared__ State s;

    cg::cluster_group cl = cg::this_cluster();
    const int tid  = threadIdx.x;
    const int lane = tid & 31;
    const int wid  = tid >> 5;
    const unsigned rank  = cl.block_rank();           // 0..15
    const bool isClass   = rank < 8;
    const unsigned chunk = rank & 7;
    const unsigned gbase = isClass ? 0u : 8u;
    const unsigned peer  = rank ^ 8u;
    const int batch = blockIdx.x / CLN;

    const size_t off = (size_t)batch * CC * TT + (size_t)chunk * CHUNK * TT;
    const float* X = (isClass ? cls_all : qry_all) + off;
    float*       O = (isClass ? oc_all  : oq_all ) + off;

    // Class CTAs compute m_q (= qbar . ct[u]) -> run the QUERY-side MLP, and
    // symmetrically for query CTAs. (Verified mapping, rel_err 6e-9 in R2.)
    const float* w1 = isClass ? qw1 : cw1;
    const float* b1 = isClass ? qb1 : cb1;
    const float* w2 = isClass ? qw2 : cw2;
    const float* b2 = isClass ? qb2 : cb2;

    // ---- TMA bulk load of my tile ------------------------------------------
    const unsigned tileA = su32(tile);
    const unsigned mb    = su32(&s.mbar);
    if (tid == 0) mbar_init(mb, 1);
    __syncthreads();
    if (tid == 0) {
        mbar_expect_tx(mb, TILE_BYTES);
        bulk_g2s(tileA, X, TILE_BYTES, mb);
    }
    mbar_wait(mb, 0);

    // ---- Phase 1: sumsq partial over my channels ---------------------------
    if (tid < TT) {
        float acc = 0.f;
#pragma unroll 8
        for (int c = 0; c < CHUNK; ++c) {
            float v = tile[c * TT + tid];
            acc = fmaf(v, v, acc);
        }
        s.p0[tid] = acc;
    }
    cl.sync();  // S1

    // ---- invn (group reduce over 8 ranks) + bar (local row reduce) ---------
    if (tid < TT) {
        float ss = 0.f;
#pragma unroll
        for (unsigned i = 0; i < 8; ++i)
            ss += cl.map_shared_rank(s.p0, gbase + i)[tid];
        s.invn[tid] = 1.f / fmaxf(sqrtf(ss), 1e-12f);
    }
    __syncthreads();
    for (int c = wid; c < CHUNK; c += NW) {
        float acc = 0.f;
        for (int t = lane; t < TT; t += 32)
            acc = fmaf(tile[c * TT + t], s.invn[t], acc);
        acc = warp_sum(acc);
        if (lane == 0) s.bar[c] = acc * (1.f / (float)TT);
    }
    cl.sync();  // S2

    // ---- m partial: sum_c peer_bar[c] * tile[c][t] -------------------------
    {
        const float* pbar = cl.map_shared_rank(s.bar, peer);
        if (tid < CHUNK) s.obar[tid] = pbar[tid];
    }
    __syncthreads();
    if (tid < TT) {
        float acc = 0.f;
#pragma unroll 8
        for (int c = 0; c < CHUNK; ++c)
            acc = fmaf(s.obar[c], tile[c * TT + tid], acc);
        s.mpart[tid] = acc;
    }
    cl.sync();  // S3

    // ---- m reduce, tiny MLP -> kw = k * invn, then v (local row reduce) ----
    if (tid < TT) {
        float mm = 0.f;
#pragma unroll
        for (unsigned i = 0; i < 8; ++i)
            mm += cl.map_shared_rank(s.mpart, gbase + i)[tid];
        s.m[tid] = mm * s.invn[tid];
    }
    __syncthreads();
    // hidden: h[hh] = relu(b1[hh] + sum_t m[t]*w1[t,hh]); 256 thr = 32 hh x 8 splits
    {
        const int hh = tid >> 3;     // 0..31
        const int tg = tid & 7;      // 0..7
        float acc = 0.f;
        for (int t = tg; t < TT; t += 8)
            acc = fmaf(s.m[t], w1[t * 32 + hh], acc);
#pragma unroll
        for (int o = 4; o; o >>= 1) acc += __shfl_xor_sync(0xffffffffu, acc, o);
        if (tg == 0) s.h[hh] = fmaxf(acc + b1[hh], 0.f);
    }
    __syncthreads();
    if (tid < TT) {
        float acc = b2[tid];
#pragma unroll
        for (int hh = 0; hh < 32; ++hh)
            acc = fmaf(s.h[hh], w2[hh * TT + tid], acc);
        s.kw[tid] = acc * s.invn[tid];
    }
    __syncthreads();
    for (int c = wid; c < CHUNK; c += NW) {
        float acc = 0.f;
        for (int t = lane; t < TT; t += 32)
            acc = fmaf(tile[c * TT + t], s.kw[t], acc);
        acc = warp_sum(acc);
        if (lane == 0) s.v[c] = acc;
    }
    cl.sync();  // S4

    // ---- logit partial: sum_c peer_v[c] * tile[c][t] -----------------------
    {
        const float* pv = cl.map_shared_rank(s.v, peer);
        if (tid < CHUNK) s.obar[tid] = pv[tid];
    }
    __syncthreads();
    if (tid < TT) {
        float acc = 0.f;
#pragma unroll 8
        for (int c = 0; c < CHUNK; ++c)
            acc = fmaf(s.obar[c], tile[c * TT + tid], acc);
        s.lp[tid] = acc;
    }
    cl.sync();  // S5

    // ---- logits reduce, softmax (replicated within group) ------------------
    if (tid < TT) {
        float ll = 0.f;
#pragma unroll
        for (unsigned i = 0; i < 8; ++i)
            ll += cl.map_shared_rank(s.lp, gbase + i)[tid];
        s.m[tid] = ll * s.invn[tid] * 40.f;   // /0.025
    }
    __syncthreads();
    if (wid == 0) {
        float v = -3.4e38f;
        for (int t = lane; t < TT; t += 32) v = fmaxf(v, s.m[t]);
        v = warp_max(v);
        if (lane == 0) s.red[0] = v;
    }
    __syncthreads();
    if (tid < TT) s.m[tid] = expf(s.m[tid] - s.red[0]);
    __syncthreads();
    if (wid == 0) {
        float v = 0.f;
        for (int t = lane; t < TT; t += 32) v += s.m[t];
        v = warp_sum(v);
        if (lane == 0) s.red[1] = v;
    }
    __syncthreads();
    if (tid < TT) s.a4[tid] = 1.f + s.m[tid] / s.red[1];
    __syncthreads();

    // ---- output: out = tile * (1 + attn[token]) ----------------------------
    {
        const float4* t4 = reinterpret_cast<const float4*>(tile);
        const float4* a4 = reinterpret_cast<const float4*>(s.a4);
        float4* o4 = reinterpret_cast<float4*>(O);
        const int N4 = TILE_ELEMS / 4;   // 3920; channel row = 49 float4
        for (int i = tid; i < N4; i += TPB) {
            float4 v = t4[i];
            float4 a = a4[i % 49];
            v.x *= a.x; v.y *= a.y; v.z *= a.z; v.w *= a.w;
            o4[i] = v;
        }
    }

    cl.sync();  // keep SMEM alive until all cluster peers finished remote reads
}

extern "C" void kernel_launch(void* const* d_in, const int* in_sizes, int n_in,
                              void* d_out, int out_size) {
    const float* cls = (const float*)d_in[0];
    const float* qry = (const float*)d_in[1];
    const float* cw1 = (const float*)d_in[2];
    const float* cb1 = (const float*)d_in[3];
    const float* cw2 = (const float*)d_in[4];
    const float* cb2 = (const float*)d_in[5];
    const float* qw1 = (const float*)d_in[6];
    const float* qb1 = (const float*)d_in[7];
    const float* qw2 = (const float*)d_in[8];
    const float* qb2 = (const float*)d_in[9];

    const int B = in_sizes[0] / (CC * TT);  // 512
    float* oc = (float*)d_out;
    float* oq = oc + (size_t)B * CC * TT;

    cudaFuncSetAttribute(cross_attn_cluster16,
                         cudaFuncAttributeMaxDynamicSharedMemorySize, TILE_BYTES);
    cudaFuncSetAttribute(cross_attn_cluster16,
                         cudaFuncAttributeNonPortableClusterSizeAllowed, 1);

    cudaLaunchConfig_t cfg = {};
    cfg.gridDim  = dim3(B * CLN, 1, 1);
    cfg.blockDim = dim3(TPB, 1, 1);
    cfg.dynamicSmemBytes = TILE_BYTES;
    cudaLaunchAttribute attrs[1];
    attrs[0].id = cudaLaunchAttributeClusterDimension;
    attrs[0].val.clusterDim = {CLN, 1, 1};
    cfg.attrs = attrs;
    cfg.numAttrs = 1;

    cudaLaunchKernelEx(&cfg, cross_attn_cluster16,
                       cls, qry, cw1, cb1, cw2, cb2, qw1, qb1, qw2, qb2, oc, oq);
}